// round 3
// baseline (speedup 1.0000x reference)
#include <cuda_runtime.h>
#include <cuda_bf16.h>
#include <cuda_fp16.h>
#include <mma.h>
#include <math.h>

using namespace nvcuda;

#define NB 8
#define CC 256
#define HWD 4096
#define NHW (NB*HWD)

// ---------------- scratch (static __device__ globals; no allocation) -------
__device__ float          g_ymu[CC];
__device__ __nv_bfloat16  g_xt[(size_t)NB*HWD*CC];     // (n, i, c) K-major bf16
__device__ __nv_bfloat16  g_yt[(size_t)NB*HWD*CC];     // (n, j, c)
__device__ __half         g_cos[(size_t)NB*HWD*HWD];   // (n, i, j) fp16, 268MB
__device__ float          g_a[NB*HWD];                 // 2/(dmin+eps)
__device__ float          g_L[NB*HWD];                 // log-sum-exp per row
__device__ float          g_gpart[4*NB*HWD];           // column-max partials
__device__ float          g_lossb[NB];

// ---------------- reduction helpers ----------------------------------------
__device__ __forceinline__ float warpRedSum(float v) {
    #pragma unroll
    for (int o = 16; o; o >>= 1) v += __shfl_xor_sync(0xFFFFFFFFu, v, o);
    return v;
}
__device__ __forceinline__ float warpRedMax(float v) {
    #pragma unroll
    for (int o = 16; o; o >>= 1) v = fmaxf(v, __shfl_xor_sync(0xFFFFFFFFu, v, o));
    return v;
}

// ---------------- kernel 1: per-channel mean of y over N,H,W ---------------
__global__ void ymu_kernel(const float* __restrict__ y) {
    int c = blockIdx.x;
    float s = 0.f;
    for (int idx = threadIdx.x; idx < NHW; idx += 256) {
        int n = idx >> 12, hw = idx & 4095;
        s += y[((size_t)(n*CC + c))*HWD + hw];
    }
    __shared__ float sm[8];
    s = warpRedSum(s);
    int wid = threadIdx.x >> 5, lane = threadIdx.x & 31;
    if (lane == 0) sm[wid] = s;
    __syncthreads();
    if (threadIdx.x == 0) {
        float t = 0.f;
        #pragma unroll
        for (int k = 0; k < 8; k++) t += sm[k];
        g_ymu[c] = t / (float)NHW;
    }
}

// ---------------- kernel 2: center + L2-normalize over C + transpose -------
// One block = (n, 32 pixels). Emits bf16 K-major rows for the GEMM.
__global__ void norm_transpose_kernel(const float* __restrict__ x,
                                      const float* __restrict__ y) {
    __shared__ float tile[CC*33];
    __shared__ float part[256];
    __shared__ float inv[32];
    int hw0 = blockIdx.x * 32;
    int n   = blockIdx.y;
    const float* src = blockIdx.z ? y : x;
    __nv_bfloat16* dst = blockIdx.z ? g_yt : g_xt;

    int t = threadIdx.x;
    int w = t & 31, p = t >> 5;
    #pragma unroll
    for (int k = 0; k < 32; k++) {
        int c = k*8 + p;
        tile[c*33 + w] = src[((size_t)(n*CC + c))*HWD + hw0 + w] - g_ymu[c];
    }
    __syncthreads();
    float s = 0.f;
    #pragma unroll
    for (int k = 0; k < 32; k++) {
        float v = tile[(p*32 + k)*33 + w];
        s += v*v;
    }
    part[t] = s;
    __syncthreads();
    if (t < 32) {
        float tot = 0.f;
        #pragma unroll
        for (int q = 0; q < 8; q++) tot += part[q*32 + t];
        inv[t] = rsqrtf(tot);
    }
    __syncthreads();
    for (int idx = t; idx < 32*CC; idx += 256) {
        int ww = idx >> 8, c = idx & 255;
        dst[((size_t)(n*HWD + hw0 + ww))*CC + c] =
            __float2bfloat16(tile[c*33 + ww] * inv[ww]);
    }
}

// ---------------- kernel 3: batched NT GEMM (bf16 wmma, fp32 accum) --------
// C[b,i,j] = sum_c XT[b,i,c] * YT[b,j,c]; writes fp16 matrix.
__global__ void gemm_kernel() {
    __shared__ __align__(128) __nv_bfloat16 As[128*40];
    __shared__ __align__(128) __nv_bfloat16 Bs[128*40];

    int b  = blockIdx.z;
    int i0 = blockIdx.y * 128;
    int j0 = blockIdx.x * 128;
    int tid  = threadIdx.x;
    int warp = tid >> 5, lane = tid & 31;
    int wm = warp >> 2;   // 0..1 (64 rows each)
    int wn = warp & 3;    // 0..3 (32 cols each)

    const __nv_bfloat16* Ab = g_xt + (size_t)b*HWD*CC;
    const __nv_bfloat16* Bb = g_yt + (size_t)b*HWD*CC;

    wmma::fragment<wmma::accumulator,16,16,16,float> acc[4][2];
    #pragma unroll
    for (int fm = 0; fm < 4; fm++)
        #pragma unroll
        for (int fn = 0; fn < 2; fn++) wmma::fill_fragment(acc[fm][fn], 0.f);

    for (int k0 = 0; k0 < CC; k0 += 32) {
        #pragma unroll
        for (int r = 0; r < 2; r++) {
            int idx = tid + r*256;
            int row = idx >> 2, seg = idx & 3;
            *reinterpret_cast<uint4*>(&As[row*40 + seg*8]) =
                *reinterpret_cast<const uint4*>(&Ab[(size_t)(i0+row)*CC + k0 + seg*8]);
            *reinterpret_cast<uint4*>(&Bs[row*40 + seg*8]) =
                *reinterpret_cast<const uint4*>(&Bb[(size_t)(j0+row)*CC + k0 + seg*8]);
        }
        __syncthreads();
        #pragma unroll
        for (int kk = 0; kk < 32; kk += 16) {
            wmma::fragment<wmma::matrix_a,16,16,16,__nv_bfloat16,wmma::row_major> af[4];
            wmma::fragment<wmma::matrix_b,16,16,16,__nv_bfloat16,wmma::col_major> bf[2];
            #pragma unroll
            for (int fm = 0; fm < 4; fm++)
                wmma::load_matrix_sync(af[fm], &As[(wm*64 + fm*16)*40 + kk], 40);
            #pragma unroll
            for (int fn = 0; fn < 2; fn++)
                wmma::load_matrix_sync(bf[fn], &Bs[(wn*32 + fn*16)*40 + kk], 40);
            #pragma unroll
            for (int fm = 0; fm < 4; fm++)
                #pragma unroll
                for (int fn = 0; fn < 2; fn++)
                    wmma::mma_sync(acc[fm][fn], af[fm], bf[fn], acc[fm][fn]);
        }
        __syncthreads();
    }

    // epilogue: fp32 frag -> smem -> fp16 global (16B stores)
    float* scr = reinterpret_cast<float*>(As) + warp*256;
    __half* Cb = g_cos + (size_t)b*HWD*HWD;
    #pragma unroll
    for (int fm = 0; fm < 4; fm++) {
        #pragma unroll
        for (int fn = 0; fn < 2; fn++) {
            wmma::store_matrix_sync(scr, acc[fm][fn], 16, wmma::mem_row_major);
            __syncwarp();
            int r = lane >> 1, cs = (lane & 1)*8;
            __align__(16) __half h[8];
            #pragma unroll
            for (int q = 0; q < 8; q++) h[q] = __float2half(scr[r*16 + cs + q]);
            size_t gi = (size_t)(i0 + wm*64 + fm*16 + r);
            size_t gj = (size_t)(j0 + wn*32 + fn*16 + cs);
            *reinterpret_cast<uint4*>(&Cb[gi*HWD + gj]) =
                *reinterpret_cast<const uint4*>(h);
            __syncwarp();
        }
    }
}

// ---------------- kernel 4: per-row maxcos -> a_i, and LSE -> L_i ----------
// One block per (b, i); row = 4096 fp16 = one global read, held in registers.
__global__ void row_stats_kernel() {
    int i = blockIdx.x, b = blockIdx.y;
    const uint4* r = reinterpret_cast<const uint4*>(
        g_cos + ((size_t)b*HWD + i)*HWD);
    uint4 q0 = r[threadIdx.x];
    uint4 q1 = r[threadIdx.x + 256];
    float v[16];
    {
        const __half2* h0 = reinterpret_cast<const __half2*>(&q0);
        const __half2* h1 = reinterpret_cast<const __half2*>(&q1);
        #pragma unroll
        for (int t = 0; t < 4; t++) {
            float2 f = __half22float2(h0[t]); v[2*t]   = f.x; v[2*t+1]   = f.y;
            f        = __half22float2(h1[t]); v[8+2*t] = f.x; v[8+2*t+1] = f.y;
        }
    }
    float mx = v[0];
    #pragma unroll
    for (int t = 1; t < 16; t++) mx = fmaxf(mx, v[t]);

    __shared__ float sm[8];
    __shared__ float bc;
    int wid = threadIdx.x >> 5, lane = threadIdx.x & 31;
    mx = warpRedMax(mx);
    if (lane == 0) sm[wid] = mx;
    __syncthreads();
    if (threadIdx.x == 0) {
        float m = sm[0];
        #pragma unroll
        for (int k = 1; k < 8; k++) m = fmaxf(m, sm[k]);
        bc = m;
    }
    __syncthreads();
    mx = bc;
    float a = 2.f / ((1.f - mx) + 1e-6f);   // exponent e_ij = a*(cos-1)
    float s = 0.f;
    #pragma unroll
    for (int t = 0; t < 16; t++) s += expf(fmaf(a, v[t], -a));
    __syncthreads();
    s = warpRedSum(s);
    if (lane == 0) sm[wid] = s;
    __syncthreads();
    if (threadIdx.x == 0) {
        float tot = 0.f;
        #pragma unroll
        for (int k = 0; k < 8; k++) tot += sm[k];
        g_a[b*HWD + i] = a;
        g_L[b*HWD + i] = logf(tot);
    }
}

// ---------------- kernel 5: column max of (e_ij - L_i), partial over i ----
// Each thread owns TWO adjacent columns via half2 loads (coalesced 4B).
__global__ void colmax_kernel() {
    __shared__ float a_s[1024];
    __shared__ float c_s[1024];
    int j2 = blockIdx.x*256 + threadIdx.x;   // half2 index: columns 2*j2, 2*j2+1
    int ch = blockIdx.y;                     // i-chunk (1024 rows)
    int b  = blockIdx.z;
    for (int ii = threadIdx.x; ii < 1024; ii += 256) {
        int i = ch*1024 + ii;
        float a = g_a[b*HWD + i];
        a_s[ii] = a;
        c_s[ii] = a + g_L[b*HWD + i];        // e - L = a*cos - (a + L)
    }
    __syncthreads();
    const __half2* C = reinterpret_cast<const __half2*>(
        g_cos + (size_t)b*HWD*HWD + (size_t)(ch*1024)*HWD) + j2;
    float g0 = -3.4e38f, g1 = -3.4e38f;
    #pragma unroll 8
    for (int i = 0; i < 1024; i++) {
        float2 v = __half22float2(C[(size_t)i*(HWD/2)]);
        float a = a_s[i], c = c_s[i];
        g0 = fmaxf(g0, fmaf(a, v.x, -c));
        g1 = fmaxf(g1, fmaf(a, v.y, -c));
    }
    g_gpart[(ch*NB + b)*HWD + 2*j2]     = g0;
    g_gpart[(ch*NB + b)*HWD + 2*j2 + 1] = g1;
}

// ---------------- kernel 6: per-batch mean_j exp(g_j) -> -log --------------
__global__ void batch_reduce_kernel() {
    int b = blockIdx.x;
    float s = 0.f;
    for (int j = threadIdx.x; j < HWD; j += 256) {
        float g = g_gpart[(0*NB + b)*HWD + j];
        g = fmaxf(g, g_gpart[(1*NB + b)*HWD + j]);
        g = fmaxf(g, g_gpart[(2*NB + b)*HWD + j]);
        g = fmaxf(g, g_gpart[(3*NB + b)*HWD + j]);
        s += expf(g);
    }
    __shared__ float sm[8];
    int wid = threadIdx.x >> 5, lane = threadIdx.x & 31;
    s = warpRedSum(s);
    if (lane == 0) sm[wid] = s;
    __syncthreads();
    if (threadIdx.x == 0) {
        float tot = 0.f;
        #pragma unroll
        for (int k = 0; k < 8; k++) tot += sm[k];
        g_lossb[b] = -logf(tot / (float)HWD + 1e-6f);
    }
}

// ---------------- kernel 7: final mean over batch ---------------------------
__global__ void final_kernel(float* __restrict__ out) {
    if (threadIdx.x == 0) {
        float s = 0.f;
        #pragma unroll
        for (int b = 0; b < NB; b++) s += g_lossb[b];
        out[0] = s / (float)NB;
    }
}

// ---------------- launch ----------------------------------------------------
extern "C" void kernel_launch(void* const* d_in, const int* in_sizes, int n_in,
                              void* d_out, int out_size) {
    const float* x = (const float*)d_in[0];
    const float* y = (const float*)d_in[1];
    float* out = (float*)d_out;

    ymu_kernel<<<CC, 256>>>(y);
    norm_transpose_kernel<<<dim3(128, NB, 2), 256>>>(x, y);
    gemm_kernel<<<dim3(32, 32, NB), 256>>>();
    row_stats_kernel<<<dim3(HWD, NB), 256>>>();
    colmax_kernel<<<dim3(8, 4, NB), 256>>>();
    batch_reduce_kernel<<<NB, 256>>>();
    final_kernel<<<1, 32>>>(out);
}